// round 1
// baseline (speedup 1.0000x reference)
#include <cuda_runtime.h>

// Problem constants
#define NSITES   262144      // 4 * 65536
#define CCH      64          // C_IN == C_OUT == 64
#define BN_EPS_F 1e-3f
#define RBLK     512         // partial-reduction blocks for BN stats

// -------- scratch (no allocations allowed; __device__ globals) --------
__device__ float g_psum[RBLK * CCH];
__device__ float g_psq [RBLK * CCH];
__device__ float g_scale[CCH];
__device__ float g_shift[CCH];

// ======================================================================
// Conv: out[n, co] = bias[co] + sum_k sum_ci feat[nbr[n,k], ci] * W[k,ci,co]
// CTA tile: 64 sites x 64 couts, 256 threads, 4x4 register blocking.
// ======================================================================
__global__ __launch_bounds__(256) void conv_kernel(
    const float* __restrict__ feat,    // [N, 64]
    const float* __restrict__ weight,  // [9, 64, 64]  (k, cin, cout)
    const float* __restrict__ bias,    // [64]
    const int*   __restrict__ nbr,     // [N, 9]
    float*       __restrict__ out)     // [N, 64]
{
    __shared__ float Wsm[64 * 64];        // 16 KB: W[k] as [cin][cout]
    __shared__ float Fsm[64 * 68];        // 17 KB: gathered features, padded row=68
    __shared__ int   Idx[64 * 9];         // neighbor indices for this tile

    const int tid  = threadIdx.x;
    const int base = blockIdx.x * 64;     // first site of this tile
    const int tx   = tid & 15;            // cout group (4 couts)
    const int ty   = tid >> 4;            // site group (4 sites)

    // preload all 64*9 neighbor indices (coalesced: nbr is row-major [N][9])
    #pragma unroll
    for (int i = tid; i < 64 * 9; i += 256)
        Idx[i] = nbr[(size_t)base * 9 + i];

    float acc[4][4];
    #pragma unroll
    for (int i = 0; i < 4; ++i)
        #pragma unroll
        for (int j = 0; j < 4; ++j) acc[i][j] = 0.0f;

    for (int k = 0; k < 9; ++k) {
        __syncthreads();   // protect previous iteration's SMEM use (also covers Idx on k=0)

        // stage W[k]: 4096 floats = 1024 float4, 4 per thread (coalesced)
        const float4* wsrc = (const float4*)(weight + (size_t)k * 4096);
        #pragma unroll
        for (int i = 0; i < 4; ++i) {
            int e = tid + i * 256;
            ((float4*)Wsm)[e] = wsrc[e];
        }

        // gather feature rows: 64 sites x 16 float4 each
        #pragma unroll
        for (int i = 0; i < 4; ++i) {
            int e    = tid + i * 256;     // 0..1023
            int site = e >> 4;
            int c4   = e & 15;
            int row  = Idx[site * 9 + k];
            float4 v = make_float4(0.f, 0.f, 0.f, 0.f);
            if (row >= 0)
                v = ((const float4*)(feat + (size_t)row * 64))[c4];
            *(float4*)&Fsm[site * 68 + c4 * 4] = v;
        }
        __syncthreads();

        // 64-deep K loop, 4x4 register tile
        #pragma unroll 16
        for (int kk = 0; kk < 64; ++kk) {
            float4 b = *(const float4*)&Wsm[kk * 64 + tx * 4];
            #pragma unroll
            for (int i = 0; i < 4; ++i) {
                float a = Fsm[(ty * 4 + i) * 68 + kk];
                acc[i][0] += a * b.x;
                acc[i][1] += a * b.y;
                acc[i][2] += a * b.z;
                acc[i][3] += a * b.w;
            }
        }
    }

    const float4 bv = *(const float4*)&bias[tx * 4];
    #pragma unroll
    for (int i = 0; i < 4; ++i) {
        int row = base + ty * 4 + i;
        float4 o = make_float4(acc[i][0] + bv.x, acc[i][1] + bv.y,
                               acc[i][2] + bv.z, acc[i][3] + bv.w);
        *(float4*)&out[(size_t)row * 64 + tx * 4] = o;
    }
}

// ======================================================================
// BN stage 1: per-block partial sum / sum-of-squares per channel.
// 512 blocks x 256 threads; each block covers 512 rows; thread = (group, ch).
// ======================================================================
__global__ __launch_bounds__(256) void bn_reduce1(const float* __restrict__ out)
{
    const int ch = threadIdx.x & 63;
    const int g  = threadIdx.x >> 6;          // 0..3
    const int rows = NSITES / RBLK;           // 512
    const int r0   = blockIdx.x * rows;

    float s = 0.f, q = 0.f;
    for (int r = g; r < rows; r += 4) {
        float x = out[(size_t)(r0 + r) * 64 + ch];
        s += x;
        q += x * x;
    }

    __shared__ float ssum[4][64];
    __shared__ float ssq [4][64];
    ssum[g][ch] = s;
    ssq [g][ch] = q;
    __syncthreads();

    if (g == 0) {
        s = ssum[0][ch] + ssum[1][ch] + ssum[2][ch] + ssum[3][ch];
        q = ssq [0][ch] + ssq [1][ch] + ssq [2][ch] + ssq [3][ch];
        g_psum[blockIdx.x * 64 + ch] = s;
        g_psq [blockIdx.x * 64 + ch] = q;
    }
}

// ======================================================================
// BN stage 2: finalize mean/var -> per-channel scale & shift. 1 block, 64 thr.
// ======================================================================
__global__ void bn_reduce2(const float* __restrict__ gamma,
                           const float* __restrict__ beta)
{
    const int ch = threadIdx.x;
    float s = 0.f, q = 0.f;
    for (int i = 0; i < RBLK; ++i) {
        s += g_psum[i * 64 + ch];
        q += g_psq [i * 64 + ch];
    }
    const float inv_n = 1.0f / (float)NSITES;
    float mean = s * inv_n;
    float var  = q * inv_n - mean * mean;
    float sc   = gamma[ch] * rsqrtf(var + BN_EPS_F);
    g_scale[ch] = sc;
    g_shift[ch] = beta[ch] - mean * sc;
}

// ======================================================================
// BN stage 3: elementwise apply, float4-vectorized.
// i-th float4 covers channels [4*(i%16), +4).
// ======================================================================
__global__ __launch_bounds__(256) void bn_apply(const float* __restrict__ out,
                                                float* __restrict__ outbn)
{
    size_t i = (size_t)blockIdx.x * 256 + threadIdx.x;  // float4 index
    float4 v = ((const float4*)out)[i];
    int cb = ((int)(i & 15)) * 4;
    float4 sc = *(const float4*)&g_scale[cb];
    float4 sh = *(const float4*)&g_shift[cb];
    ((float4*)outbn)[i] = make_float4(v.x * sc.x + sh.x,
                                      v.y * sc.y + sh.y,
                                      v.z * sc.z + sh.z,
                                      v.w * sc.w + sh.w);
}

// ======================================================================
// Launch: inputs per metadata order:
//   0 features [N,64] f32, 1 weight [9,64,64] f32, 2 bias [64] f32,
//   3 gamma [64] f32, 4 beta [64] f32, 5 neighbor_idx [N,9] i32
// Output: float32, out_size = 2*N*64 (out, then out_bn).
// ======================================================================
extern "C" void kernel_launch(void* const* d_in, const int* in_sizes, int n_in,
                              void* d_out, int out_size)
{
    const float* feat  = (const float*)d_in[0];
    const float* w     = (const float*)d_in[1];
    const float* bias  = (const float*)d_in[2];
    const float* gamma = (const float*)d_in[3];
    const float* beta  = (const float*)d_in[4];
    const int*   nbr   = (const int*)  d_in[5];

    float* out   = (float*)d_out;
    float* outbn = out + (size_t)NSITES * CCH;

    conv_kernel<<<NSITES / 64, 256>>>(feat, w, bias, nbr, out);
    bn_reduce1 <<<RBLK, 256>>>(out);
    bn_reduce2 <<<1, 64>>>(gamma, beta);
    bn_apply   <<<(NSITES * CCH / 4) / 256, 256>>>(out, outbn);
}

// round 4
// speedup vs baseline: 2.0706x; 2.0706x over previous
#include <cuda_runtime.h>
#include <cuda_bf16.h>
#include <cstdint>

#define NSITES   262144
#define CCH      64
#define BN_EPS_F 1e-3f
#define RBLK     512

// ---------------- scratch (__device__ globals; no allocations) ----------------
__device__ __align__(128) __nv_bfloat16 g_fhi[NSITES * 64];
__device__ __align__(128) __nv_bfloat16 g_flo[NSITES * 64];
__device__ __align__(128) __nv_bfloat16 g_whi[9 * 64 * 64];   // [k][cout][cin]
__device__ __align__(128) __nv_bfloat16 g_wlo[9 * 64 * 64];
__device__ float g_psum[RBLK * CCH];
__device__ float g_psq [RBLK * CCH];
__device__ float g_scale[CCH];
__device__ float g_shift[CCH];

// ---------------- helpers ----------------
__device__ __forceinline__ uint32_t smem_u32(const void* p) {
    uint32_t a;
    asm("{ .reg .u64 t; cvta.to.shared.u64 t, %1; cvt.u32.u64 %0, t; }" : "=r"(a) : "l"(p));
    return a;
}
__device__ __forceinline__ void ldsm_x4(uint32_t& r0, uint32_t& r1, uint32_t& r2, uint32_t& r3,
                                        uint32_t addr) {
    asm volatile("ldmatrix.sync.aligned.m8n8.x4.shared.b16 {%0,%1,%2,%3}, [%4];"
                 : "=r"(r0), "=r"(r1), "=r"(r2), "=r"(r3) : "r"(addr));
}
__device__ __forceinline__ void mma_bf16(float* d, const uint32_t* a, const uint32_t* b) {
    asm volatile(
        "mma.sync.aligned.m16n8k16.row.col.f32.bf16.bf16.f32 "
        "{%0,%1,%2,%3}, {%4,%5,%6,%7}, {%8,%9}, {%0,%1,%2,%3};"
        : "+f"(d[0]), "+f"(d[1]), "+f"(d[2]), "+f"(d[3])
        : "r"(a[0]), "r"(a[1]), "r"(a[2]), "r"(a[3]), "r"(b[0]), "r"(b[1]));
}

// ---------------- precompute: split features / weights into bf16 hi+lo ----------------
__global__ __launch_bounds__(256) void split_feat(const float* __restrict__ f)
{
    size_t i = ((size_t)blockIdx.x * 256 + threadIdx.x) * 8;
    float4 a = *(const float4*)(f + i);
    float4 b = *(const float4*)(f + i + 4);
    float v[8] = {a.x, a.y, a.z, a.w, b.x, b.y, b.z, b.w};
    __nv_bfloat16 h[8], l[8];
    #pragma unroll
    for (int j = 0; j < 8; ++j) {
        h[j] = __float2bfloat16(v[j]);
        l[j] = __float2bfloat16(v[j] - __bfloat162float(h[j]));
    }
    *(uint4*)(g_fhi + i) = *(uint4*)h;
    *(uint4*)(g_flo + i) = *(uint4*)l;
}

__global__ __launch_bounds__(256) void split_w(const float* __restrict__ w)
{
    int i = blockIdx.x * 256 + threadIdx.x;          // 0..36863
    int k = i >> 12, ci = (i >> 6) & 63, co = i & 63;
    float v = w[i];
    __nv_bfloat16 h = __float2bfloat16(v);
    __nv_bfloat16 l = __float2bfloat16(v - __bfloat162float(h));
    int o = (k << 12) + (co << 6) + ci;              // [k][cout][cin] for .col B operand
    g_whi[o] = h;
    g_wlo[o] = l;
}

// ---------------- conv via ldmatrix + mma.sync (HMMA) ----------------
// SMEM (static, 48 KB exactly), SW128-style XOR swizzle, rows of 128 B:
//   A_hi [128][64] bf16 @ 0       (16384)
//   A_lo [128][64] bf16 @ 16384   (16384)
//   B_hi [64][64]  bf16 @ 32768   (8192)   rows = cout, cols = cin
//   B_lo [64][64]  bf16 @ 40960   (8192)
#define OFF_AHI 0
#define OFF_ALO 16384
#define OFF_BHI 32768
#define OFF_BLO 40960

__global__ __launch_bounds__(256) void conv_hmma(
    const int*   __restrict__ nbr,
    const float* __restrict__ bias,
    float*       __restrict__ out)
{
    __shared__ __align__(128) char smem[49152];
    const uint32_t sb = smem_u32(smem);

    const int tid  = threadIdx.x;
    const int wid  = tid >> 5;
    const int l    = tid & 31;
    const int WM   = wid >> 1;           // 0..3 : 32-row slice
    const int WN   = wid & 1;            // 0..1 : 32-col slice
    const int base = blockIdx.x * 128;

    const int site = tid >> 1;           // 0..127 (2 threads per site)
    const int half = tid & 1;            // which 32-channel half

    float d[2][4][4];
    #pragma unroll
    for (int mt = 0; mt < 2; ++mt)
        #pragma unroll
        for (int nt = 0; nt < 4; ++nt)
            #pragma unroll
            for (int j = 0; j < 4; ++j) d[mt][nt][j] = 0.0f;

    // per-lane ldmatrix address components
    const int aRow   = l & 15;
    const int aCB    = (l >> 4) & 1;                 // chunk sub-offset along k
    const int aKey   = l & 7;                        // swizzle key = row & 7
    uint32_t aOffRow[2];
    #pragma unroll
    for (int mt = 0; mt < 2; ++mt)
        aOffRow[mt] = (uint32_t)((WM * 32 + mt * 16 + aRow) * 128);

    const int bRowIn = ((l >> 4) & 1) * 8 + (l & 7); // row within 16-row pair block
    const int bCB    = (l >> 3) & 1;
    uint32_t bOffRow[2];
    #pragma unroll
    for (int p = 0; p < 2; ++p)
        bOffRow[p] = (uint32_t)((WN * 32 + p * 16 + bRowIn) * 128);

    for (int k = 0; k < 9; ++k) {
        __syncthreads();   // previous iteration's ldmatrix reads complete

        // --- gather A rows (bf16 hi/lo), swizzled; zeros for idx<0 ---
        {
            int row = nbr[(size_t)(base + site) * 9 + k];
            char* aH = smem + OFF_AHI + site * 128;
            char* aL = smem + OFF_ALO + site * 128;
            int key = site & 7;
            if (row >= 0) {
                const uint4* srcH = (const uint4*)(g_fhi + (size_t)row * 64 + half * 32);
                const uint4* srcL = (const uint4*)(g_flo + (size_t)row * 64 + half * 32);
                #pragma unroll
                for (int j = 0; j < 4; ++j) {
                    int chunk = half * 4 + j;
                    int sw = (chunk ^ key) * 16;
                    *(uint4*)(aH + sw) = srcH[j];
                    *(uint4*)(aL + sw) = srcL[j];
                }
            } else {
                uint4 z = make_uint4(0, 0, 0, 0);
                #pragma unroll
                for (int j = 0; j < 4; ++j) {
                    int chunk = half * 4 + j;
                    int sw = (chunk ^ key) * 16;
                    *(uint4*)(aH + sw) = z;
                    *(uint4*)(aL + sw) = z;
                }
            }
        }
        // --- stage B = W[k] as [cout][cin], swizzled ---
        {
            const uint4* wsH = (const uint4*)(g_whi + k * 4096);
            const uint4* wsL = (const uint4*)(g_wlo + k * 4096);
            #pragma unroll
            for (int j = 0; j < 2; ++j) {
                int e = tid * 2 + j;                 // 0..511 (uint4 = 8 bf16)
                int r = e >> 3, chunk = e & 7;
                int sw = r * 128 + (chunk ^ (r & 7)) * 16;
                *(uint4*)(smem + OFF_BHI + sw) = wsH[e];
                *(uint4*)(smem + OFF_BLO + sw) = wsL[e];
            }
        }
        __syncthreads();

        // --- 4 k-steps of 16; 3-term split MMAs ---
        #pragma unroll
        for (int ks = 0; ks < 4; ++ks) {
            uint32_t ahi[2][4], alo[2][4], bhi[2][4], blo[2][4];
            #pragma unroll
            for (int mt = 0; mt < 2; ++mt) {
                uint32_t sw = (uint32_t)(((ks * 2 + aCB) ^ aKey) << 4);
                ldsm_x4(ahi[mt][0], ahi[mt][1], ahi[mt][2], ahi[mt][3],
                        sb + OFF_AHI + aOffRow[mt] + sw);
                ldsm_x4(alo[mt][0], alo[mt][1], alo[mt][2], alo[mt][3],
                        sb + OFF_ALO + aOffRow[mt] + sw);
            }
            #pragma unroll
            for (int p = 0; p < 2; ++p) {
                uint32_t sw = (uint32_t)(((ks * 2 + bCB) ^ aKey) << 4);
                ldsm_x4(bhi[p][0], bhi[p][1], bhi[p][2], bhi[p][3],
                        sb + OFF_BHI + bOffRow[p] + sw);
                ldsm_x4(blo[p][0], blo[p][1], blo[p][2], blo[p][3],
                        sb + OFF_BLO + bOffRow[p] + sw);
            }
            #pragma unroll
            for (int mt = 0; mt < 2; ++mt)
                #pragma unroll
                for (int p = 0; p < 2; ++p)
                    #pragma unroll
                    for (int q = 0; q < 2; ++q) {
                        int nt = p * 2 + q;
                        mma_bf16(d[mt][nt], ahi[mt], &bhi[p][2 * q]);
                        mma_bf16(d[mt][nt], ahi[mt], &blo[p][2 * q]);
                        mma_bf16(d[mt][nt], alo[mt], &bhi[p][2 * q]);
                    }
        }
    }

    // --- epilogue: bias + store ---
    #pragma unroll
    for (int nt = 0; nt < 4; ++nt) {
        int col = WN * 32 + nt * 8 + 2 * (l & 3);
        float b0 = bias[col], b1 = bias[col + 1];
        #pragma unroll
        for (int mt = 0; mt < 2; ++mt) {
            int r0 = base + WM * 32 + mt * 16 + (l >> 2);
            float2 v0 = make_float2(d[mt][nt][0] + b0, d[mt][nt][1] + b1);
            float2 v1 = make_float2(d[mt][nt][2] + b0, d[mt][nt][3] + b1);
            *(float2*)(out + (size_t)r0 * 64 + col)       = v0;
            *(float2*)(out + (size_t)(r0 + 8) * 64 + col) = v1;
        }
    }
}

// ---------------- BN (unchanged, proven) ----------------
__global__ __launch_bounds__(256) void bn_reduce1(const float* __restrict__ out)
{
    const int ch = threadIdx.x & 63;
    const int g  = threadIdx.x >> 6;
    const int rows = NSITES / RBLK;
    const int r0   = blockIdx.x * rows;

    float s = 0.f, q = 0.f;
    for (int r = g; r < rows; r += 4) {
        float x = out[(size_t)(r0 + r) * 64 + ch];
        s += x; q += x * x;
    }
    __shared__ float ssum[4][64];
    __shared__ float ssq [4][64];
    ssum[g][ch] = s; ssq[g][ch] = q;
    __syncthreads();
    if (g == 0) {
        s = ssum[0][ch] + ssum[1][ch] + ssum[2][ch] + ssum[3][ch];
        q = ssq [0][ch] + ssq [1][ch] + ssq [2][ch] + ssq [3][ch];
        g_psum[blockIdx.x * 64 + ch] = s;
        g_psq [blockIdx.x * 64 + ch] = q;
    }
}

__global__ void bn_reduce2(const float* __restrict__ gamma,
                           const float* __restrict__ beta)
{
    const int ch = threadIdx.x;
    float s = 0.f, q = 0.f;
    for (int i = 0; i < RBLK; ++i) {
        s += g_psum[i * 64 + ch];
        q += g_psq [i * 64 + ch];
    }
    const float inv_n = 1.0f / (float)NSITES;
    float mean = s * inv_n;
    float var  = q * inv_n - mean * mean;
    float sc   = gamma[ch] * rsqrtf(var + BN_EPS_F);
    g_scale[ch] = sc;
    g_shift[ch] = beta[ch] - mean * sc;
}

__global__ __launch_bounds__(256) void bn_apply(const float* __restrict__ out,
                                                float* __restrict__ outbn)
{
    size_t i = (size_t)blockIdx.x * 256 + threadIdx.x;
    float4 v = ((const float4*)out)[i];
    int cb = ((int)(i & 15)) * 4;
    float4 sc = *(const float4*)&g_scale[cb];
    float4 sh = *(const float4*)&g_shift[cb];
    ((float4*)outbn)[i] = make_float4(v.x * sc.x + sh.x, v.y * sc.y + sh.y,
                                      v.z * sc.z + sh.z, v.w * sc.w + sh.w);
}

// ---------------- launch ----------------
extern "C" void kernel_launch(void* const* d_in, const int* in_sizes, int n_in,
                              void* d_out, int out_size)
{
    const float* feat  = (const float*)d_in[0];
    const float* w     = (const float*)d_in[1];
    const float* bias  = (const float*)d_in[2];
    const float* gamma = (const float*)d_in[3];
    const float* beta  = (const float*)d_in[4];
    const int*   nbr   = (const int*)  d_in[5];

    float* out   = (float*)d_out;
    float* outbn = out + (size_t)NSITES * CCH;

    split_feat<<<NSITES * 64 / 8 / 256, 256>>>(feat);
    split_w   <<<9 * 64 * 64 / 256, 256>>>(w);
    conv_hmma <<<NSITES / 128, 256>>>(nbr, bias, out);
    bn_reduce1<<<RBLK, 256>>>(out);
    bn_reduce2<<<1, 64>>>(gamma, beta);
    bn_apply  <<<(NSITES * CCH / 4) / 256, 256>>>(out, outbn);
}

// round 5
// speedup vs baseline: 2.1811x; 1.0533x over previous
#include <cuda_runtime.h>
#include <cuda_bf16.h>
#include <cstdint>

#define NSITES   262144
#define CCH      64
#define BN_EPS_F 1e-3f
#define NCTA     2048        // conv CTAs (= NSITES/128), also BN partials count

// ---------------- scratch (__device__ globals; no allocations) ----------------
__device__ __align__(128) __nv_bfloat16 g_fhi[NSITES * 64];
__device__ __align__(128) __nv_bfloat16 g_flo[NSITES * 64];
__device__ __align__(128) __nv_bfloat16 g_whi[9 * 64 * 64];   // [k][cout][cin]
__device__ __align__(128) __nv_bfloat16 g_wlo[9 * 64 * 64];
__device__ float g_psum[NCTA * CCH];
__device__ float g_psq [NCTA * CCH];
__device__ float g_scale[CCH];
__device__ float g_shift[CCH];

// ---------------- helpers ----------------
__device__ __forceinline__ uint32_t smem_u32(const void* p) {
    uint32_t a;
    asm("{ .reg .u64 t; cvta.to.shared.u64 t, %1; cvt.u32.u64 %0, t; }" : "=r"(a) : "l"(p));
    return a;
}
__device__ __forceinline__ void ldsm_x4(uint32_t& r0, uint32_t& r1, uint32_t& r2, uint32_t& r3,
                                        uint32_t addr) {
    asm volatile("ldmatrix.sync.aligned.m8n8.x4.shared.b16 {%0,%1,%2,%3}, [%4];"
                 : "=r"(r0), "=r"(r1), "=r"(r2), "=r"(r3) : "r"(addr));
}
__device__ __forceinline__ void mma_bf16(float* d, const uint32_t* a, const uint32_t* b) {
    asm volatile(
        "mma.sync.aligned.m16n8k16.row.col.f32.bf16.bf16.f32 "
        "{%0,%1,%2,%3}, {%4,%5,%6,%7}, {%8,%9}, {%0,%1,%2,%3};"
        : "+f"(d[0]), "+f"(d[1]), "+f"(d[2]), "+f"(d[3])
        : "r"(a[0]), "r"(a[1]), "r"(a[2]), "r"(a[3]), "r"(b[0]), "r"(b[1]));
}
#define CP_ASYNC16(dst, src, sz) \
    asm volatile("cp.async.cg.shared.global [%0], [%1], 16, %2;" \
                 :: "r"(dst), "l"(src), "r"(sz) : "memory")
#define CP_COMMIT()  asm volatile("cp.async.commit_group;" ::: "memory")
#define CP_WAIT1()   asm volatile("cp.async.wait_group 1;" ::: "memory")

// ---------------- precompute: split features / weights into bf16 hi+lo ----------------
__global__ __launch_bounds__(256) void split_feat(const float* __restrict__ f)
{
    size_t i = ((size_t)blockIdx.x * 256 + threadIdx.x) * 8;
    float4 a = *(const float4*)(f + i);
    float4 b = *(const float4*)(f + i + 4);
    float v[8] = {a.x, a.y, a.z, a.w, b.x, b.y, b.z, b.w};
    __nv_bfloat16 h[8], l[8];
    #pragma unroll
    for (int j = 0; j < 8; ++j) {
        h[j] = __float2bfloat16(v[j]);
        l[j] = __float2bfloat16(v[j] - __bfloat162float(h[j]));
    }
    *(uint4*)(g_fhi + i) = *(uint4*)h;
    *(uint4*)(g_flo + i) = *(uint4*)l;
}

__global__ __launch_bounds__(256) void split_w(const float* __restrict__ w)
{
    int i = blockIdx.x * 256 + threadIdx.x;          // 0..36863
    int k = i >> 12, ci = (i >> 6) & 63, co = i & 63;
    float v = w[i];
    __nv_bfloat16 h = __float2bfloat16(v);
    __nv_bfloat16 l = __float2bfloat16(v - __bfloat162float(h));
    int o = (k << 12) + (co << 6) + ci;              // [k][cout][cin] for .col B operand
    g_whi[o] = h;
    g_wlo[o] = l;
}

// ---------------- conv via cp.async-pipelined ldmatrix + mma.sync ----------------
// Dynamic SMEM (96 KB): A stages 2 x 32768 (hi@0, lo@16384); B stages @65536, 2 x 16384
#define STAGE_A   32768
#define OFF_B     65536
#define STAGE_B   16384
#define SMEM_CONV 98304

struct ConvSm { char raw[1]; };

__global__ __launch_bounds__(256, 2) void conv_hmma(
    const int*   __restrict__ nbr,
    const float* __restrict__ bias,
    float*       __restrict__ out)
{
    extern __shared__ __align__(128) char smem[];
    const uint32_t sb = smem_u32(smem);

    const int tid  = threadIdx.x;
    const int wid  = tid >> 5;
    const int l    = tid & 31;
    const int WM   = wid >> 1;           // 0..3 : 32-row slice
    const int WN   = wid & 1;            // 0..1 : 32-col slice
    const int base = blockIdx.x * 128;

    const int site = tid >> 1;           // 0..127 (2 threads per site)
    const int half = tid & 1;            // which 32-channel half
    const int akey = site & 7;

    // ---- gather issue lambdas (branch-free zero-fill via src-size) ----
    auto issue_A = [&](int row, int st) {
        uint32_t aH = sb + st * STAGE_A + (uint32_t)(site * 128);
        uint32_t aL = aH + 16384;
        size_t r = (size_t)(row >= 0 ? row : 0);
        const char* srcH = (const char*)(g_fhi + r * 64 + half * 32);
        const char* srcL = (const char*)(g_flo + r * 64 + half * 32);
        int sz = (row >= 0) ? 16 : 0;
        #pragma unroll
        for (int j = 0; j < 4; ++j) {
            int chunk = half * 4 + j;
            uint32_t sw = (uint32_t)((chunk ^ akey) * 16);
            CP_ASYNC16(aH + sw, srcH + j * 16, sz);
            CP_ASYNC16(aL + sw, srcL + j * 16, sz);
        }
    };
    auto issue_B = [&](int k, int st) {
        const char* wH = (const char*)(g_whi + k * 4096);
        const char* wL = (const char*)(g_wlo + k * 4096);
        uint32_t bH = sb + OFF_B + st * STAGE_B;
        #pragma unroll
        for (int j = 0; j < 2; ++j) {
            int e = tid * 2 + j;                 // 0..511 (16B chunks)
            int r = e >> 3, chunk = e & 7;
            uint32_t sw = (uint32_t)(r * 128 + (chunk ^ (r & 7)) * 16);
            CP_ASYNC16(bH + sw, wH + e * 16, 16);
            CP_ASYNC16(bH + 8192 + sw, wL + e * 16, 16);
        }
    };

    // ---- prologue: taps 0,1 in flight ----
    #pragma unroll
    for (int kk = 0; kk < 2; ++kk) {
        int row = nbr[(size_t)(base + site) * 9 + kk];
        issue_A(row, kk);
        issue_B(kk, kk);
        CP_COMMIT();
    }

    float d[2][4][4];
    #pragma unroll
    for (int mt = 0; mt < 2; ++mt)
        #pragma unroll
        for (int nt = 0; nt < 4; ++nt)
            #pragma unroll
            for (int j = 0; j < 4; ++j) d[mt][nt][j] = 0.0f;

    // per-lane ldmatrix address components (same mapping as R4 — proven)
    const int aRow = l & 15;
    const int aCB  = (l >> 4) & 1;
    const int aKey = l & 7;
    uint32_t aOffRow[2];
    #pragma unroll
    for (int mt = 0; mt < 2; ++mt)
        aOffRow[mt] = (uint32_t)((WM * 32 + mt * 16 + aRow) * 128);
    const int bRowIn = ((l >> 4) & 1) * 8 + (l & 7);
    const int bCB    = (l >> 3) & 1;
    uint32_t bOffRow[2];
    #pragma unroll
    for (int p = 0; p < 2; ++p)
        bOffRow[p] = (uint32_t)((WN * 32 + p * 16 + bRowIn) * 128);

    for (int k = 0; k < 9; ++k) {
        const int kk = k + 2;
        int rowN = -1;
        if (kk < 9) rowN = nbr[(size_t)(base + site) * 9 + kk];   // prefetch early

        CP_WAIT1();                 // tap k resident
        __syncthreads();

        const uint32_t aBase = sb + (uint32_t)((k & 1) * STAGE_A);
        const uint32_t bBase = sb + OFF_B + (uint32_t)((k & 1) * STAGE_B);

        #pragma unroll
        for (int ks = 0; ks < 4; ++ks) {
            uint32_t ahi[2][4], alo[2][4], bhi[2][4], blo[2][4];
            uint32_t swA = (uint32_t)(((ks * 2 + aCB) ^ aKey) << 4);
            uint32_t swB = (uint32_t)(((ks * 2 + bCB) ^ aKey) << 4);
            #pragma unroll
            for (int mt = 0; mt < 2; ++mt) {
                ldsm_x4(ahi[mt][0], ahi[mt][1], ahi[mt][2], ahi[mt][3],
                        aBase + aOffRow[mt] + swA);
                ldsm_x4(alo[mt][0], alo[mt][1], alo[mt][2], alo[mt][3],
                        aBase + 16384 + aOffRow[mt] + swA);
            }
            #pragma unroll
            for (int p = 0; p < 2; ++p) {
                ldsm_x4(bhi[p][0], bhi[p][1], bhi[p][2], bhi[p][3],
                        bBase + bOffRow[p] + swB);
                ldsm_x4(blo[p][0], blo[p][1], blo[p][2], blo[p][3],
                        bBase + 8192 + bOffRow[p] + swB);
            }
            #pragma unroll
            for (int mt = 0; mt < 2; ++mt)
                #pragma unroll
                for (int p = 0; p < 2; ++p)
                    #pragma unroll
                    for (int q = 0; q < 2; ++q) {
                        int nt = p * 2 + q;
                        mma_bf16(d[mt][nt], ahi[mt], &bhi[p][2 * q]);
                        mma_bf16(d[mt][nt], ahi[mt], &blo[p][2 * q]);
                        mma_bf16(d[mt][nt], alo[mt], &bhi[p][2 * q]);
                    }
        }
        __syncthreads();            // stage free before refill

        if (kk < 9) {
            issue_A(rowN, kk & 1);
            issue_B(kk, kk & 1);
        }
        CP_COMMIT();                // commit every iteration (may be empty)
    }

    // ---- epilogue: bias add, store, per-CTA BN partials ----
    float colS[4][2], colQ[4][2];
    #pragma unroll
    for (int nt = 0; nt < 4; ++nt) {
        int col = WN * 32 + nt * 8 + 2 * (l & 3);
        float b0 = bias[col], b1 = bias[col + 1];
        float s0 = 0.f, q0 = 0.f, s1 = 0.f, q1 = 0.f;
        #pragma unroll
        for (int mt = 0; mt < 2; ++mt) {
            int r0 = base + WM * 32 + mt * 16 + (l >> 2);
            float x0 = d[mt][nt][0] + b0, x1 = d[mt][nt][1] + b1;
            float x2 = d[mt][nt][2] + b0, x3 = d[mt][nt][3] + b1;
            *(float2*)(out + (size_t)r0 * 64 + col)       = make_float2(x0, x1);
            *(float2*)(out + (size_t)(r0 + 8) * 64 + col) = make_float2(x2, x3);
            s0 += x0 + x2;  q0 += x0 * x0 + x2 * x2;
            s1 += x1 + x3;  q1 += x1 * x1 + x3 * x3;
        }
        colS[nt][0] = s0; colS[nt][1] = s1;
        colQ[nt][0] = q0; colQ[nt][1] = q1;
    }
    // reduce across the 8 lanes sharing a column (l>>2 varies): xor 4,8,16
    #pragma unroll
    for (int off = 4; off <= 16; off <<= 1)
        #pragma unroll
        for (int nt = 0; nt < 4; ++nt)
            #pragma unroll
            for (int c = 0; c < 2; ++c) {
                colS[nt][c] += __shfl_xor_sync(0xffffffffu, colS[nt][c], off);
                colQ[nt][c] += __shfl_xor_sync(0xffffffffu, colQ[nt][c], off);
            }

    // overlay warp partial buffers on A smem (all MMA reads done; sync above)
    float* warpS = (float*)smem;            // [8][32]
    float* warpQ = (float*)(smem + 1024);   // [8][32]
    if (l < 4) {
        #pragma unroll
        for (int nt = 0; nt < 4; ++nt) {
            warpS[wid * 32 + nt * 8 + 2 * l]     = colS[nt][0];
            warpS[wid * 32 + nt * 8 + 2 * l + 1] = colS[nt][1];
            warpQ[wid * 32 + nt * 8 + 2 * l]     = colQ[nt][0];
            warpQ[wid * 32 + nt * 8 + 2 * l + 1] = colQ[nt][1];
        }
    }
    __syncthreads();
    if (tid < 128) {
        int ch = tid & 63, kind = tid >> 6;
        int wn = ch >> 5, idx = ch & 31;
        const float* src = kind ? warpQ : warpS;
        float v = src[(0 * 2 + wn) * 32 + idx] + src[(1 * 2 + wn) * 32 + idx]
                + src[(2 * 2 + wn) * 32 + idx] + src[(3 * 2 + wn) * 32 + idx];
        if (kind) g_psq [blockIdx.x * 64 + ch] = v;
        else      g_psum[blockIdx.x * 64 + ch] = v;
    }
}

// ---------------- BN finalize: sum 2048 partials per channel (deterministic) ----------------
__global__ __launch_bounds__(256) void bn_finalize(const float* __restrict__ gamma,
                                                   const float* __restrict__ beta)
{
    __shared__ float ss[4][64], sq[4][64];
    const int ch = threadIdx.x & 63;
    const int g  = threadIdx.x >> 6;
    float s = 0.f, q = 0.f;
    for (int i = g; i < NCTA; i += 4) {
        s += g_psum[i * 64 + ch];
        q += g_psq [i * 64 + ch];
    }
    ss[g][ch] = s; sq[g][ch] = q;
    __syncthreads();
    if (g == 0) {
        s = ss[0][ch] + ss[1][ch] + ss[2][ch] + ss[3][ch];
        q = sq[0][ch] + sq[1][ch] + sq[2][ch] + sq[3][ch];
        const float inv_n = 1.0f / (float)NSITES;
        float mean = s * inv_n;
        float var  = q * inv_n - mean * mean;
        float sc   = gamma[ch] * rsqrtf(var + BN_EPS_F);
        g_scale[ch] = sc;
        g_shift[ch] = beta[ch] - mean * sc;
    }
}

// ---------------- BN apply ----------------
__global__ __launch_bounds__(256) void bn_apply(const float* __restrict__ out,
                                                float* __restrict__ outbn)
{
    size_t i = (size_t)blockIdx.x * 256 + threadIdx.x;
    float4 v = ((const float4*)out)[i];
    int cb = ((int)(i & 15)) * 4;
    float4 sc = *(const float4*)&g_scale[cb];
    float4 sh = *(const float4*)&g_shift[cb];
    ((float4*)outbn)[i] = make_float4(v.x * sc.x + sh.x, v.y * sc.y + sh.y,
                                      v.z * sc.z + sh.z, v.w * sc.w + sh.w);
}

// ---------------- launch ----------------
extern "C" void kernel_launch(void* const* d_in, const int* in_sizes, int n_in,
                              void* d_out, int out_size)
{
    const float* feat  = (const float*)d_in[0];
    const float* w     = (const float*)d_in[1];
    const float* bias  = (const float*)d_in[2];
    const float* gamma = (const float*)d_in[3];
    const float* beta  = (const float*)d_in[4];
    const int*   nbr   = (const int*)  d_in[5];

    float* out   = (float*)d_out;
    float* outbn = out + (size_t)NSITES * CCH;

    cudaFuncSetAttribute(conv_hmma, cudaFuncAttributeMaxDynamicSharedMemorySize, SMEM_CONV);

    split_feat <<<NSITES * 64 / 8 / 256, 256>>>(feat);
    split_w    <<<9 * 64 * 64 / 256, 256>>>(w);
    conv_hmma  <<<NCTA, 256, SMEM_CONV>>>(nbr, bias, out);
    bn_finalize<<<1, 256>>>(gamma, beta);
    bn_apply   <<<(NSITES * CCH / 4) / 256, 256>>>(out, outbn);
}

// round 6
// speedup vs baseline: 3.2579x; 1.4937x over previous
#include <cuda_runtime.h>
#include <cuda_fp16.h>
#include <cstdint>

#define NSITES   262144
#define CCH      64
#define BN_EPS_F 1e-3f
#define NCTA     2048        // conv CTAs (= NSITES/128), BN partials count
#define FIN1     64          // stage-1 finalize blocks

// ---------------- scratch (__device__ globals; no allocations) ----------------
__device__ __align__(128) __half g_f16[NSITES * 64];          // features, fp16
__device__ __align__(128) __half g_whi[9 * 64 * 64];          // [k][cout][cin] hi
__device__ __align__(128) __half g_wlo[9 * 64 * 64];          // [k][cout][cin] lo
__device__ float g_psum[NCTA * CCH];
__device__ float g_psq [NCTA * CCH];
__device__ float g_ps2 [FIN1 * CCH];
__device__ float g_pq2 [FIN1 * CCH];
__device__ float g_scale[CCH];
__device__ float g_shift[CCH];

// ---------------- helpers ----------------
__device__ __forceinline__ uint32_t smem_u32(const void* p) {
    uint32_t a;
    asm("{ .reg .u64 t; cvta.to.shared.u64 t, %1; cvt.u32.u64 %0, t; }" : "=r"(a) : "l"(p));
    return a;
}
__device__ __forceinline__ void ldsm_x4(uint32_t& r0, uint32_t& r1, uint32_t& r2, uint32_t& r3,
                                        uint32_t addr) {
    asm volatile("ldmatrix.sync.aligned.m8n8.x4.shared.b16 {%0,%1,%2,%3}, [%4];"
                 : "=r"(r0), "=r"(r1), "=r"(r2), "=r"(r3) : "r"(addr));
}
__device__ __forceinline__ void mma_f16(float* d, const uint32_t* a, const uint32_t* b) {
    asm volatile(
        "mma.sync.aligned.m16n8k16.row.col.f32.f16.f16.f32 "
        "{%0,%1,%2,%3}, {%4,%5,%6,%7}, {%8,%9}, {%0,%1,%2,%3};"
        : "+f"(d[0]), "+f"(d[1]), "+f"(d[2]), "+f"(d[3])
        : "r"(a[0]), "r"(a[1]), "r"(a[2]), "r"(a[3]), "r"(b[0]), "r"(b[1]));
}
#define CP_ASYNC16(dst, src, sz) \
    asm volatile("cp.async.cg.shared.global [%0], [%1], 16, %2;" \
                 :: "r"(dst), "l"(src), "r"(sz) : "memory")
#define CP_COMMIT()  asm volatile("cp.async.commit_group;" ::: "memory")
#define CP_WAIT1()   asm volatile("cp.async.wait_group 1;" ::: "memory")

// ---------------- precompute ----------------
__global__ __launch_bounds__(256) void split_feat(const float* __restrict__ f)
{
    size_t i = ((size_t)blockIdx.x * 256 + threadIdx.x) * 8;
    float4 a = *(const float4*)(f + i);
    float4 b = *(const float4*)(f + i + 4);
    float v[8] = {a.x, a.y, a.z, a.w, b.x, b.y, b.z, b.w};
    __half h[8];
    #pragma unroll
    for (int j = 0; j < 8; ++j) h[j] = __float2half_rn(v[j]);
    *(uint4*)(g_f16 + i) = *(uint4*)h;
}

__global__ __launch_bounds__(256) void split_w(const float* __restrict__ w)
{
    int i = blockIdx.x * 256 + threadIdx.x;          // 0..36863
    int k = i >> 12, ci = (i >> 6) & 63, co = i & 63;
    float v = w[i];
    __half h = __float2half_rn(v);
    __half l = __float2half_rn(v - __half2float(h));
    int o = (k << 12) + (co << 6) + ci;              // [k][cout][cin] for .col B
    g_whi[o] = h;
    g_wlo[o] = l;
}

// ---------------- conv: cp.async pipeline + fp16 HMMA, 2-term W split ----------------
// Dynamic SMEM (64 KB): A stages 2 x 16384 @ 0 ; B stages 2 x 16384 @ 32768 (hi 8K + lo 8K)
#define STAGE_A   16384
#define OFF_B     32768
#define STAGE_B   16384
#define SMEM_CONV 65536

__global__ __launch_bounds__(256, 2) void conv_hmma(
    const int*   __restrict__ nbr,
    const float* __restrict__ bias,
    float*       __restrict__ out)
{
    extern __shared__ __align__(128) char smem[];
    const uint32_t sb = smem_u32(smem);

    const int tid  = threadIdx.x;
    const int wid  = tid >> 5;
    const int l    = tid & 31;
    const int WM   = wid >> 1;           // 0..3 : 32-row slice
    const int WN   = wid & 1;            // 0..1 : 32-col slice
    const int base = blockIdx.x * 128;

    const int site = tid >> 1;           // 2 threads per site
    const int half = tid & 1;
    const int akey = site & 7;

    auto issue_A = [&](int row, int st) {
        uint32_t aD = sb + st * STAGE_A + (uint32_t)(site * 128);
        size_t r = (size_t)(row >= 0 ? row : 0);
        const char* src = (const char*)(g_f16 + r * 64 + half * 32);
        int sz = (row >= 0) ? 16 : 0;
        #pragma unroll
        for (int j = 0; j < 4; ++j) {
            int chunk = half * 4 + j;
            uint32_t sw = (uint32_t)((chunk ^ akey) * 16);
            CP_ASYNC16(aD + sw, src + j * 16, sz);
        }
    };
    auto issue_B = [&](int k, int st) {
        const char* wH = (const char*)(g_whi + k * 4096);
        const char* wL = (const char*)(g_wlo + k * 4096);
        uint32_t bD = sb + OFF_B + st * STAGE_B;
        #pragma unroll
        for (int j = 0; j < 2; ++j) {
            int e = tid * 2 + j;                 // 0..511 (16B chunks)
            int r = e >> 3, chunk = e & 7;
            uint32_t sw = (uint32_t)(r * 128 + (chunk ^ (r & 7)) * 16);
            CP_ASYNC16(bD + sw, wH + e * 16, 16);
            CP_ASYNC16(bD + 8192 + sw, wL + e * 16, 16);
        }
    };

    // prologue: taps 0,1 in flight
    #pragma unroll
    for (int kk = 0; kk < 2; ++kk) {
        int row = nbr[(size_t)(base + site) * 9 + kk];
        issue_A(row, kk);
        issue_B(kk, kk);
        CP_COMMIT();
    }

    float d[2][4][4];
    #pragma unroll
    for (int mt = 0; mt < 2; ++mt)
        #pragma unroll
        for (int nt = 0; nt < 4; ++nt)
            #pragma unroll
            for (int j = 0; j < 4; ++j) d[mt][nt][j] = 0.0f;

    const int aRow = l & 15;
    const int aCB  = (l >> 4) & 1;
    const int aKey = l & 7;
    uint32_t aOffRow[2];
    #pragma unroll
    for (int mt = 0; mt < 2; ++mt)
        aOffRow[mt] = (uint32_t)((WM * 32 + mt * 16 + aRow) * 128);
    const int bRowIn = ((l >> 4) & 1) * 8 + (l & 7);
    const int bCB    = (l >> 3) & 1;
    uint32_t bOffRow[2];
    #pragma unroll
    for (int p = 0; p < 2; ++p)
        bOffRow[p] = (uint32_t)((WN * 32 + p * 16 + bRowIn) * 128);

    for (int k = 0; k < 9; ++k) {
        const int kk = k + 2;
        int rowN = -1;
        if (kk < 9) rowN = nbr[(size_t)(base + site) * 9 + kk];

        CP_WAIT1();
        __syncthreads();

        const uint32_t aBase = sb + (uint32_t)((k & 1) * STAGE_A);
        const uint32_t bBase = sb + OFF_B + (uint32_t)((k & 1) * STAGE_B);

        #pragma unroll
        for (int ks = 0; ks < 4; ++ks) {
            uint32_t a[2][4], bh[2][4], bl[2][4];
            uint32_t swA = (uint32_t)(((ks * 2 + aCB) ^ aKey) << 4);
            uint32_t swB = (uint32_t)(((ks * 2 + bCB) ^ aKey) << 4);
            #pragma unroll
            for (int mt = 0; mt < 2; ++mt)
                ldsm_x4(a[mt][0], a[mt][1], a[mt][2], a[mt][3],
                        aBase + aOffRow[mt] + swA);
            #pragma unroll
            for (int p = 0; p < 2; ++p) {
                ldsm_x4(bh[p][0], bh[p][1], bh[p][2], bh[p][3],
                        bBase + bOffRow[p] + swB);
                ldsm_x4(bl[p][0], bl[p][1], bl[p][2], bl[p][3],
                        bBase + 8192 + bOffRow[p] + swB);
            }
            #pragma unroll
            for (int mt = 0; mt < 2; ++mt)
                #pragma unroll
                for (int p = 0; p < 2; ++p)
                    #pragma unroll
                    for (int q = 0; q < 2; ++q) {
                        int nt = p * 2 + q;
                        mma_f16(d[mt][nt], a[mt], &bh[p][2 * q]);
                        mma_f16(d[mt][nt], a[mt], &bl[p][2 * q]);
                    }
        }
        __syncthreads();

        if (kk < 9) {
            issue_A(rowN, kk & 1);
            issue_B(kk, kk & 1);
        }
        CP_COMMIT();
    }

    // ---- epilogue: bias add, store, per-CTA BN partials ----
    float colS[4][2], colQ[4][2];
    #pragma unroll
    for (int nt = 0; nt < 4; ++nt) {
        int col = WN * 32 + nt * 8 + 2 * (l & 3);
        float b0 = bias[col], b1 = bias[col + 1];
        float s0 = 0.f, q0 = 0.f, s1 = 0.f, q1 = 0.f;
        #pragma unroll
        for (int mt = 0; mt < 2; ++mt) {
            int r0 = base + WM * 32 + mt * 16 + (l >> 2);
            float x0 = d[mt][nt][0] + b0, x1 = d[mt][nt][1] + b1;
            float x2 = d[mt][nt][2] + b0, x3 = d[mt][nt][3] + b1;
            *(float2*)(out + (size_t)r0 * 64 + col)       = make_float2(x0, x1);
            *(float2*)(out + (size_t)(r0 + 8) * 64 + col) = make_float2(x2, x3);
            s0 += x0 + x2;  q0 += x0 * x0 + x2 * x2;
            s1 += x1 + x3;  q1 += x1 * x1 + x3 * x3;
        }
        colS[nt][0] = s0; colS[nt][1] = s1;
        colQ[nt][0] = q0; colQ[nt][1] = q1;
    }
    #pragma unroll
    for (int off = 4; off <= 16; off <<= 1)
        #pragma unroll
        for (int nt = 0; nt < 4; ++nt)
            #pragma unroll
            for (int c = 0; c < 2; ++c) {
                colS[nt][c] += __shfl_xor_sync(0xffffffffu, colS[nt][c], off);
                colQ[nt][c] += __shfl_xor_sync(0xffffffffu, colQ[nt][c], off);
            }

    float* warpS = (float*)smem;            // [8][32]
    float* warpQ = (float*)(smem + 1024);   // [8][32]
    if (l < 4) {
        #pragma unroll
        for (int nt = 0; nt < 4; ++nt) {
            warpS[wid * 32 + nt * 8 + 2 * l]     = colS[nt][0];
            warpS[wid * 32 + nt * 8 + 2 * l + 1] = colS[nt][1];
            warpQ[wid * 32 + nt * 8 + 2 * l]     = colQ[nt][0];
            warpQ[wid * 32 + nt * 8 + 2 * l + 1] = colQ[nt][1];
        }
    }
    __syncthreads();
    if (tid < 128) {
        int ch = tid & 63, kind = tid >> 6;
        int wn = ch >> 5, idx = ch & 31;
        const float* src = kind ? warpQ : warpS;
        float v = src[(0 * 2 + wn) * 32 + idx] + src[(1 * 2 + wn) * 32 + idx]
                + src[(2 * 2 + wn) * 32 + idx] + src[(3 * 2 + wn) * 32 + idx];
        if (kind) g_psq [blockIdx.x * 64 + ch] = v;
        else      g_psum[blockIdx.x * 64 + ch] = v;
    }
}

// ---------------- BN finalize stage 1: 64 blocks x 32 partials each ----------------
__global__ __launch_bounds__(256) void bn_fin1()
{
    __shared__ float ss[4][64], sq[4][64];
    const int ch = threadIdx.x & 63;
    const int g  = threadIdx.x >> 6;
    float s = 0.f, q = 0.f;
    #pragma unroll
    for (int i = g; i < 32; i += 4) {
        int idx = (blockIdx.x * 32 + i) * 64 + ch;
        s += g_psum[idx];
        q += g_psq [idx];
    }
    ss[g][ch] = s; sq[g][ch] = q;
    __syncthreads();
    if (g == 0) {
        g_ps2[blockIdx.x * 64 + ch] = ss[0][ch] + ss[1][ch] + ss[2][ch] + ss[3][ch];
        g_pq2[blockIdx.x * 64 + ch] = sq[0][ch] + sq[1][ch] + sq[2][ch] + sq[3][ch];
    }
}

// ---------------- BN finalize stage 2: sum 64, compute scale/shift ----------------
__global__ __launch_bounds__(256) void bn_fin2(const float* __restrict__ gamma,
                                               const float* __restrict__ beta)
{
    __shared__ float ss[4][64], sq[4][64];
    const int ch = threadIdx.x & 63;
    const int g  = threadIdx.x >> 6;
    float s = 0.f, q = 0.f;
    #pragma unroll
    for (int i = g; i < FIN1; i += 4) {
        s += g_ps2[i * 64 + ch];
        q += g_pq2[i * 64 + ch];
    }
    ss[g][ch] = s; sq[g][ch] = q;
    __syncthreads();
    if (g == 0) {
        s = ss[0][ch] + ss[1][ch] + ss[2][ch] + ss[3][ch];
        q = sq[0][ch] + sq[1][ch] + sq[2][ch] + sq[3][ch];
        const float inv_n = 1.0f / (float)NSITES;
        float mean = s * inv_n;
        float var  = q * inv_n - mean * mean;
        float sc   = gamma[ch] * rsqrtf(var + BN_EPS_F);
        g_scale[ch] = sc;
        g_shift[ch] = beta[ch] - mean * sc;
    }
}

// ---------------- BN apply ----------------
__global__ __launch_bounds__(256) void bn_apply(const float* __restrict__ out,
                                                float* __restrict__ outbn)
{
    size_t i = (size_t)blockIdx.x * 256 + threadIdx.x;
    float4 v = ((const float4*)out)[i];
    int cb = ((int)(i & 15)) * 4;
    float4 sc = *(const float4*)&g_scale[cb];
    float4 sh = *(const float4*)&g_shift[cb];
    ((float4*)outbn)[i] = make_float4(v.x * sc.x + sh.x, v.y * sc.y + sh.y,
                                      v.z * sc.z + sh.z, v.w * sc.w + sh.w);
}

// ---------------- launch ----------------
extern "C" void kernel_launch(void* const* d_in, const int* in_sizes, int n_in,
                              void* d_out, int out_size)
{
    const float* feat  = (const float*)d_in[0];
    const float* w     = (const float*)d_in[1];
    const float* bias  = (const float*)d_in[2];
    const float* gamma = (const float*)d_in[3];
    const float* beta  = (const float*)d_in[4];
    const int*   nbr   = (const int*)  d_in[5];

    float* out   = (float*)d_out;
    float* outbn = out + (size_t)NSITES * CCH;

    cudaFuncSetAttribute(conv_hmma, cudaFuncAttributeMaxDynamicSharedMemorySize, SMEM_CONV);

    split_feat<<<NSITES * 64 / 8 / 256, 256>>>(feat);
    split_w   <<<9 * 64 * 64 / 256, 256>>>(w);
    conv_hmma <<<NCTA, 256, SMEM_CONV>>>(nbr, bias, out);
    bn_fin1   <<<FIN1, 256>>>();
    bn_fin2   <<<1, 256>>>(gamma, beta);
    bn_apply  <<<(NSITES * CCH / 4) / 256, 256>>>(out, outbn);
}

// round 7
// speedup vs baseline: 4.1137x; 1.2627x over previous
#include <cuda_runtime.h>
#include <cuda_fp16.h>
#include <cstdint>

#define NSITES   262144
#define CCH      64
#define BN_EPS_F 1e-3f
#define NCTA     2048        // conv CTAs (= NSITES/128), BN partials count
#define FIN1     64          // stage-1 finalize blocks

// ---------------- scratch (__device__ globals; no allocations) ----------------
__device__ __align__(128) __half g_f16[NSITES * 64];          // features, fp16
__device__ __align__(128) __half g_w16[9 * 64 * 64];          // [k][cout][cin]
__device__ float g_psum[NCTA * CCH];
__device__ float g_psq [NCTA * CCH];
__device__ float g_ps2 [FIN1 * CCH];
__device__ float g_pq2 [FIN1 * CCH];
__device__ float g_scale[CCH];
__device__ float g_shift[CCH];

// ---------------- helpers ----------------
__device__ __forceinline__ uint32_t smem_u32(const void* p) {
    uint32_t a;
    asm("{ .reg .u64 t; cvta.to.shared.u64 t, %1; cvt.u32.u64 %0, t; }" : "=r"(a) : "l"(p));
    return a;
}
__device__ __forceinline__ void ldsm_x4(uint32_t& r0, uint32_t& r1, uint32_t& r2, uint32_t& r3,
                                        uint32_t addr) {
    asm volatile("ldmatrix.sync.aligned.m8n8.x4.shared.b16 {%0,%1,%2,%3}, [%4];"
                 : "=r"(r0), "=r"(r1), "=r"(r2), "=r"(r3) : "r"(addr));
}
__device__ __forceinline__ void mma_f16(float* d, const uint32_t* a, const uint32_t* b) {
    asm volatile(
        "mma.sync.aligned.m16n8k16.row.col.f32.f16.f16.f32 "
        "{%0,%1,%2,%3}, {%4,%5,%6,%7}, {%8,%9}, {%0,%1,%2,%3};"
        : "+f"(d[0]), "+f"(d[1]), "+f"(d[2]), "+f"(d[3])
        : "r"(a[0]), "r"(a[1]), "r"(a[2]), "r"(a[3]), "r"(b[0]), "r"(b[1]));
}
#define CP_ASYNC16(dst, src, sz) \
    asm volatile("cp.async.cg.shared.global [%0], [%1], 16, %2;" \
                 :: "r"(dst), "l"(src), "r"(sz) : "memory")
#define CP_COMMIT()  asm volatile("cp.async.commit_group;" ::: "memory")
#define CP_WAIT1()   asm volatile("cp.async.wait_group 1;" ::: "memory")

// ---------------- precompute ----------------
__global__ __launch_bounds__(256) void split_feat(const float* __restrict__ f)
{
    size_t i = ((size_t)blockIdx.x * 256 + threadIdx.x) * 8;
    float4 a = *(const float4*)(f + i);
    float4 b = *(const float4*)(f + i + 4);
    float v[8] = {a.x, a.y, a.z, a.w, b.x, b.y, b.z, b.w};
    __half h[8];
    #pragma unroll
    for (int j = 0; j < 8; ++j) h[j] = __float2half_rn(v[j]);
    *(uint4*)(g_f16 + i) = *(uint4*)h;
}

__global__ __launch_bounds__(256) void split_w(const float* __restrict__ w)
{
    int i = blockIdx.x * 256 + threadIdx.x;          // 0..36863
    int k = i >> 12, ci = (i >> 6) & 63, co = i & 63;
    g_w16[(k << 12) + (co << 6) + ci] = __float2half_rn(w[i]);   // [k][cout][cin]
}

// ---------------- conv: cp.async pipeline + fp16 HMMA (single-term) ----------------
// Dynamic SMEM (48 KB): A stages 2 x 16384 @ 0 ; B stages 2 x 8192 @ 32768
#define STAGE_A   16384
#define OFF_B     32768
#define STAGE_B   8192
#define SMEM_CONV 49152

__global__ __launch_bounds__(256, 2) void conv_hmma(
    const int*   __restrict__ nbr,
    const float* __restrict__ bias,
    float*       __restrict__ out)
{
    extern __shared__ __align__(128) char smem[];
    const uint32_t sb = smem_u32(smem);

    const int tid  = threadIdx.x;
    const int wid  = tid >> 5;
    const int l    = tid & 31;
    const int WM   = wid >> 1;           // 0..3 : 32-row slice
    const int WN   = wid & 1;            // 0..1 : 32-col slice
    const int base = blockIdx.x * 128;

    const int site = tid >> 1;           // 2 threads per site
    const int half = tid & 1;
    const int akey = site & 7;

    auto issue_A = [&](int row, int st) {
        uint32_t aD = sb + st * STAGE_A + (uint32_t)(site * 128);
        size_t r = (size_t)(row >= 0 ? row : 0);
        const char* src = (const char*)(g_f16 + r * 64 + half * 32);
        int sz = (row >= 0) ? 16 : 0;
        #pragma unroll
        for (int j = 0; j < 4; ++j) {
            int chunk = half * 4 + j;
            uint32_t sw = (uint32_t)((chunk ^ akey) * 16);
            CP_ASYNC16(aD + sw, src + j * 16, sz);
        }
    };
    auto issue_B = [&](int k, int st) {
        const char* wS = (const char*)(g_w16 + k * 4096);
        uint32_t bD = sb + OFF_B + st * STAGE_B;
        int e = tid * 2;                     // each thread: 2 x 16B of the 8 KB tile
        #pragma unroll
        for (int j = 0; j < 2; ++j, ++e) {
            int r = e >> 3, chunk = e & 7;
            uint32_t sw = (uint32_t)(r * 128 + (chunk ^ (r & 7)) * 16);
            CP_ASYNC16(bD + sw, wS + e * 16, 16);
        }
    };

    // prologue: taps 0,1 in flight
    #pragma unroll
    for (int kk = 0; kk < 2; ++kk) {
        int row = nbr[(size_t)(base + site) * 9 + kk];
        issue_A(row, kk);
        issue_B(kk, kk);
        CP_COMMIT();
    }

    float d[2][4][4];
    #pragma unroll
    for (int mt = 0; mt < 2; ++mt)
        #pragma unroll
        for (int nt = 0; nt < 4; ++nt)
            #pragma unroll
            for (int j = 0; j < 4; ++j) d[mt][nt][j] = 0.0f;

    const int aRow = l & 15;
    const int aCB  = (l >> 4) & 1;
    const int aKey = l & 7;
    uint32_t aOffRow[2];
    #pragma unroll
    for (int mt = 0; mt < 2; ++mt)
        aOffRow[mt] = (uint32_t)((WM * 32 + mt * 16 + aRow) * 128);
    const int bRowIn = ((l >> 4) & 1) * 8 + (l & 7);
    const int bCB    = (l >> 3) & 1;
    uint32_t bOffRow[2];
    #pragma unroll
    for (int p = 0; p < 2; ++p)
        bOffRow[p] = (uint32_t)((WN * 32 + p * 16 + bRowIn) * 128);

    for (int k = 0; k < 9; ++k) {
        const int kk = k + 2;
        int rowN = -1;
        if (kk < 9) rowN = nbr[(size_t)(base + site) * 9 + kk];

        CP_WAIT1();
        __syncthreads();

        const uint32_t aBase = sb + (uint32_t)((k & 1) * STAGE_A);
        const uint32_t bBase = sb + OFF_B + (uint32_t)((k & 1) * STAGE_B);

        #pragma unroll
        for (int ks = 0; ks < 4; ++ks) {
            uint32_t a[2][4], bh[2][4];
            uint32_t swA = (uint32_t)(((ks * 2 + aCB) ^ aKey) << 4);
            uint32_t swB = (uint32_t)(((ks * 2 + bCB) ^ aKey) << 4);
            #pragma unroll
            for (int mt = 0; mt < 2; ++mt)
                ldsm_x4(a[mt][0], a[mt][1], a[mt][2], a[mt][3],
                        aBase + aOffRow[mt] + swA);
            #pragma unroll
            for (int p = 0; p < 2; ++p)
                ldsm_x4(bh[p][0], bh[p][1], bh[p][2], bh[p][3],
                        bBase + bOffRow[p] + swB);
            #pragma unroll
            for (int mt = 0; mt < 2; ++mt)
                #pragma unroll
                for (int p = 0; p < 2; ++p)
                    #pragma unroll
                    for (int q = 0; q < 2; ++q)
                        mma_f16(d[mt][p * 2 + q], a[mt], &bh[p][2 * q]);
        }
        __syncthreads();

        if (kk < 9) {
            issue_A(rowN, kk & 1);
            issue_B(kk, kk & 1);
        }
        CP_COMMIT();
    }

    // ---- epilogue: bias add, store, per-CTA BN partials ----
    float colS[4][2], colQ[4][2];
    #pragma unroll
    for (int nt = 0; nt < 4; ++nt) {
        int col = WN * 32 + nt * 8 + 2 * (l & 3);
        float b0 = bias[col], b1 = bias[col + 1];
        float s0 = 0.f, q0 = 0.f, s1 = 0.f, q1 = 0.f;
        #pragma unroll
        for (int mt = 0; mt < 2; ++mt) {
            int r0 = base + WM * 32 + mt * 16 + (l >> 2);
            float x0 = d[mt][nt][0] + b0, x1 = d[mt][nt][1] + b1;
            float x2 = d[mt][nt][2] + b0, x3 = d[mt][nt][3] + b1;
            *(float2*)(out + (size_t)r0 * 64 + col)       = make_float2(x0, x1);
            *(float2*)(out + (size_t)(r0 + 8) * 64 + col) = make_float2(x2, x3);
            s0 += x0 + x2;  q0 += x0 * x0 + x2 * x2;
            s1 += x1 + x3;  q1 += x1 * x1 + x3 * x3;
        }
        colS[nt][0] = s0; colS[nt][1] = s1;
        colQ[nt][0] = q0; colQ[nt][1] = q1;
    }
    #pragma unroll
    for (int off = 4; off <= 16; off <<= 1)
        #pragma unroll
        for (int nt = 0; nt < 4; ++nt)
            #pragma unroll
            for (int c = 0; c < 2; ++c) {
                colS[nt][c] += __shfl_xor_sync(0xffffffffu, colS[nt][c], off);
                colQ[nt][c] += __shfl_xor_sync(0xffffffffu, colQ[nt][c], off);
            }

    float* warpS = (float*)smem;            // [8][32]
    float* warpQ = (float*)(smem + 1024);   // [8][32]
    if (l < 4) {
        #pragma unroll
        for (int nt = 0; nt < 4; ++nt) {
            warpS[wid * 32 + nt * 8 + 2 * l]     = colS[nt][0];
            warpS[wid * 32 + nt * 8 + 2 * l + 1] = colS[nt][1];
            warpQ[wid * 32 + nt * 8 + 2 * l]     = colQ[nt][0];
            warpQ[wid * 32 + nt * 8 + 2 * l + 1] = colQ[nt][1];
        }
    }
    __syncthreads();
    if (tid < 128) {
        int ch = tid & 63, kind = tid >> 6;
        int wn = ch >> 5, idx = ch & 31;
        const float* src = kind ? warpQ : warpS;
        float v = src[(0 * 2 + wn) * 32 + idx] + src[(1 * 2 + wn) * 32 + idx]
                + src[(2 * 2 + wn) * 32 + idx] + src[(3 * 2 + wn) * 32 + idx];
        if (kind) g_psq [blockIdx.x * 64 + ch] = v;
        else      g_psum[blockIdx.x * 64 + ch] = v;
    }
}

// ---------------- BN finalize stage 1: 64 blocks x 32 partials ----------------
__global__ __launch_bounds__(256) void bn_fin1()
{
    __shared__ float ss[4][64], sq[4][64];
    const int ch = threadIdx.x & 63;
    const int g  = threadIdx.x >> 6;
    float s = 0.f, q = 0.f;
    #pragma unroll
    for (int i = g; i < 32; i += 4) {
        int idx = (blockIdx.x * 32 + i) * 64 + ch;
        s += g_psum[idx];
        q += g_psq [idx];
    }
    ss[g][ch] = s; sq[g][ch] = q;
    __syncthreads();
    if (g == 0) {
        g_ps2[blockIdx.x * 64 + ch] = ss[0][ch] + ss[1][ch] + ss[2][ch] + ss[3][ch];
        g_pq2[blockIdx.x * 64 + ch] = sq[0][ch] + sq[1][ch] + sq[2][ch] + sq[3][ch];
    }
}

// ---------------- BN finalize stage 2 ----------------
__global__ __launch_bounds__(256) void bn_fin2(const float* __restrict__ gamma,
                                               const float* __restrict__ beta)
{
    __shared__ float ss[4][64], sq[4][64];
    const int ch = threadIdx.x & 63;
    const int g  = threadIdx.x >> 6;
    float s = 0.f, q = 0.f;
    #pragma unroll
    for (int i = g; i < FIN1; i += 4) {
        s += g_ps2[i * 64 + ch];
        q += g_pq2[i * 64 + ch];
    }
    ss[g][ch] = s; sq[g][ch] = q;
    __syncthreads();
    if (g == 0) {
        s = ss[0][ch] + ss[1][ch] + ss[2][ch] + ss[3][ch];
        q = sq[0][ch] + sq[1][ch] + sq[2][ch] + sq[3][ch];
        const float inv_n = 1.0f / (float)NSITES;
        float mean = s * inv_n;
        float var  = q * inv_n - mean * mean;
        float sc   = gamma[ch] * rsqrtf(var + BN_EPS_F);
        g_scale[ch] = sc;
        g_shift[ch] = beta[ch] - mean * sc;
    }
}

// ---------------- BN apply: 2 float4 per thread ----------------
__global__ __launch_bounds__(256) void bn_apply(const float* __restrict__ out,
                                                float* __restrict__ outbn)
{
    size_t i0 = ((size_t)blockIdx.x * 256 + threadIdx.x) * 2;
    #pragma unroll
    for (int j = 0; j < 2; ++j) {
        size_t i = i0 + j;
        float4 v = ((const float4*)out)[i];
        int cb = ((int)(i & 15)) * 4;
        float4 sc = *(const float4*)&g_scale[cb];
        float4 sh = *(const float4*)&g_shift[cb];
        ((float4*)outbn)[i] = make_float4(v.x * sc.x + sh.x, v.y * sc.y + sh.y,
                                          v.z * sc.z + sh.z, v.w * sc.w + sh.w);
    }
}

// ---------------- launch ----------------
extern "C" void kernel_launch(void* const* d_in, const int* in_sizes, int n_in,
                              void* d_out, int out_size)
{
    const float* feat  = (const float*)d_in[0];
    const float* w     = (const float*)d_in[1];
    const float* bias  = (const float*)d_in[2];
    const float* gamma = (const float*)d_in[3];
    const float* beta  = (const float*)d_in[4];
    const int*   nbr   = (const int*)  d_in[5];

    float* out   = (float*)d_out;
    float* outbn = out + (size_t)NSITES * CCH;

    cudaFuncSetAttribute(conv_hmma, cudaFuncAttributeMaxDynamicSharedMemorySize, SMEM_CONV);

    split_feat<<<NSITES * 64 / 8 / 256, 256>>>(feat);
    split_w   <<<9 * 64 * 64 / 256, 256>>>(w);
    conv_hmma <<<NCTA, 256, SMEM_CONV>>>(nbr, bias, out);
    bn_fin1   <<<FIN1, 256>>>();
    bn_fin2   <<<1, 256>>>(gamma, beta);
    bn_apply  <<<(NSITES * CCH / 8) / 256, 256>>>(out, outbn);
}